// round 8
// baseline (speedup 1.0000x reference)
#include <cuda_runtime.h>
#include <math.h>
#include <stdint.h>

// Problem constants
#define DM   512
#define SEQ  2048
#define BB   2
#define NH   8
#define HD   64
#define MTOK (BB*SEQ)     // 4096 tokens
#define NG   (NH*BB)      // 16 attention groups

#define NORMF 0.04419417382415922f  // 1/sqrt(512)

// Scratch (static device globals; allocation is forbidden)
__device__ float g_Qp[MTOK * DM];
__device__ float g_Kp[MTOK * DM];
__device__ float g_Vp[MTOK * DM];
__device__ float g_AO[MTOK * DM];
__device__ float g_KsumP[NG * 8 * HD];

// ---------------------------------------------------------------------------
// tf32 mma.sync.m16n8k8 + split helpers
// ---------------------------------------------------------------------------
__device__ __forceinline__ void mma_tf32(float* c, const uint32_t* a, const uint32_t* b)
{
    asm volatile(
        "mma.sync.aligned.m16n8k8.row.col.f32.tf32.tf32.f32 "
        "{%0,%1,%2,%3}, {%4,%5,%6,%7}, {%8,%9}, {%0,%1,%2,%3};\n"
        : "+f"(c[0]), "+f"(c[1]), "+f"(c[2]), "+f"(c[3])
        : "r"(a[0]), "r"(a[1]), "r"(a[2]), "r"(a[3]), "r"(b[0]), "r"(b[1]));
}

__device__ __forceinline__ uint32_t to_tf32(float x)
{
    uint32_t r;
    asm("cvt.rna.tf32.f32 %0, %1;\n" : "=r"(r) : "f"(x));
    return r;
}

__device__ __forceinline__ void split_tf32(float x, float& hi, float& lo)
{
    hi = __uint_as_float(to_tf32(x));
    lo = x - hi;
}

__device__ __forceinline__ void mma3(float* c,
                                     const uint32_t* ah, const uint32_t* al,
                                     const uint32_t* bh, const uint32_t* bl)
{
    mma_tf32(c, ah, bl);
    mma_tf32(c, al, bh);
    mma_tf32(c, ah, bh);
}

// ---------------------------------------------------------------------------
// Tensor-core NT projection GEMM body (3xTF32):
// C[4096,512] = A[4096,512] @ W[512,512]^T + bias
// 128x128 CTA tile, BK=32, 8 warps (2m x 4n), warp tile 64x32.
// ---------------------------------------------------------------------------
#define PJ_S 36
#define PJ_SMEM_BYTES (2 * 128 * PJ_S * (int)sizeof(float2))   // 73728

__device__ __forceinline__ void gemm_nt_body(
    const float* __restrict__ A, const float* __restrict__ W,
    const float* __restrict__ bias, float* __restrict__ C,
    float2* sA, float2* sW)
{
    const int tid  = threadIdx.x;
    const int warp = tid >> 5;
    const int lane = tid & 31;
    const int g4   = lane >> 2;
    const int t4   = lane & 3;
    const int wm   = warp >> 2;   // 0..1
    const int wn   = warp & 3;    // 0..3
    const int m0   = blockIdx.y * 128;
    const int n0   = blockIdx.x * 128;

    float acc[4][4][4];
    #pragma unroll
    for (int mf = 0; mf < 4; mf++)
        #pragma unroll
        for (int nf = 0; nf < 4; nf++)
            #pragma unroll
            for (int c = 0; c < 4; c++) acc[mf][nf][c] = 0.f;

    for (int kt = 0; kt < DM / 32; kt++) {
        const int k0 = kt * 32;
        __syncthreads();
        #pragma unroll
        for (int i = 0; i < 4; i++) {
            int pos = tid + i * 256;          // 0..1023
            int r = pos >> 3, kq = (pos & 7) << 2;
            float4 a = *(const float4*)&A[(size_t)(m0 + r) * DM + k0 + kq];
            float4 w = *(const float4*)&W[(size_t)(n0 + r) * DM + k0 + kq];
            float4 s0, s1;
            split_tf32(a.x, s0.x, s0.y); split_tf32(a.y, s0.z, s0.w);
            split_tf32(a.z, s1.x, s1.y); split_tf32(a.w, s1.z, s1.w);
            *(float4*)&sA[r * PJ_S + kq]     = s0;
            *(float4*)&sA[r * PJ_S + kq + 2] = s1;
            split_tf32(w.x, s0.x, s0.y); split_tf32(w.y, s0.z, s0.w);
            split_tf32(w.z, s1.x, s1.y); split_tf32(w.w, s1.z, s1.w);
            *(float4*)&sW[r * PJ_S + kq]     = s0;
            *(float4*)&sW[r * PJ_S + kq + 2] = s1;
        }
        __syncthreads();

        #pragma unroll
        for (int kk = 0; kk < 4; kk++) {
            const int kc = kk * 8 + t4;
            uint32_t ah[4][4], al[4][4];
            #pragma unroll
            for (int mf = 0; mf < 4; mf++) {
                const int rb = wm * 64 + mf * 16;
                float2 e0 = sA[(rb + g4)     * PJ_S + kc];
                float2 e1 = sA[(rb + g4 + 8) * PJ_S + kc];
                float2 e2 = sA[(rb + g4)     * PJ_S + kc + 4];
                float2 e3 = sA[(rb + g4 + 8) * PJ_S + kc + 4];
                ah[mf][0] = __float_as_uint(e0.x); al[mf][0] = __float_as_uint(e0.y);
                ah[mf][1] = __float_as_uint(e1.x); al[mf][1] = __float_as_uint(e1.y);
                ah[mf][2] = __float_as_uint(e2.x); al[mf][2] = __float_as_uint(e2.y);
                ah[mf][3] = __float_as_uint(e3.x); al[mf][3] = __float_as_uint(e3.y);
            }
            #pragma unroll
            for (int nf = 0; nf < 4; nf++) {
                const int nr = wn * 32 + nf * 8 + g4;
                float2 b0 = sW[nr * PJ_S + kc];
                float2 b1 = sW[nr * PJ_S + kc + 4];
                uint32_t bh[2] = {__float_as_uint(b0.x), __float_as_uint(b1.x)};
                uint32_t bl[2] = {__float_as_uint(b0.y), __float_as_uint(b1.y)};
                #pragma unroll
                for (int mf = 0; mf < 4; mf++)
                    mma3(acc[mf][nf], ah[mf], al[mf], bh, bl);
            }
        }
    }

    #pragma unroll
    for (int nf = 0; nf < 4; nf++) {
        const int col = n0 + wn * 32 + nf * 8 + 2 * t4;
        const float b0 = bias[col], b1 = bias[col + 1];
        #pragma unroll
        for (int mf = 0; mf < 4; mf++) {
            const int r0 = m0 + wm * 64 + mf * 16 + g4;
            *(float2*)&C[(size_t)r0 * DM + col] =
                make_float2(acc[mf][nf][0] + b0, acc[mf][nf][1] + b1);
            *(float2*)&C[(size_t)(r0 + 8) * DM + col] =
                make_float2(acc[mf][nf][2] + b0, acc[mf][nf][3] + b1);
        }
    }
}

// Fused Q/K/V projection: blockIdx.z selects which projection.
__global__ __launch_bounds__(256) void gemm_qkv(
    const float* __restrict__ x, const float* __restrict__ y,
    const float* __restrict__ q_w, const float* __restrict__ q_b,
    const float* __restrict__ k_w, const float* __restrict__ k_b,
    const float* __restrict__ v_w, const float* __restrict__ v_b,
    float* __restrict__ Qp, float* __restrict__ Kp, float* __restrict__ Vp)
{
    extern __shared__ float2 pj_sm[];
    const float *A, *W, *bias;
    float* C;
    if (blockIdx.z == 0)      { A = x; W = q_w; bias = q_b; C = Qp; }
    else if (blockIdx.z == 1) { A = y; W = k_w; bias = k_b; C = Kp; }
    else                      { A = y; W = v_w; bias = v_b; C = Vp; }
    gemm_nt_body(A, W, bias, C, pj_sm, pj_sm + 128 * PJ_S);
}

// Output projection
__global__ __launch_bounds__(256) void gemm_oproj(
    const float* __restrict__ A, const float* __restrict__ W,
    const float* __restrict__ bias, float* __restrict__ C)
{
    extern __shared__ float2 pj_sm[];
    gemm_nt_body(A, W, bias, C, pj_sm, pj_sm + 128 * PJ_S);
}

// ---------------------------------------------------------------------------
// K column-sum partials
// ---------------------------------------------------------------------------
__global__ __launch_bounds__(256) void ksum_kernel(const float* __restrict__ Kp,
                                                   float* __restrict__ out)
{
    const int g  = blockIdx.x;
    const int ch = blockIdx.y;
    const int d  = threadIdx.x & 63;
    const int rc = threadIdx.x >> 6;
    const float* Kg = Kp + ((size_t)g * SEQ + ch * 256) * HD;
    float s = 0.f;
    #pragma unroll 8
    for (int r = rc; r < 256; r += 4) s += Kg[r * HD + d];
    __shared__ float red[256];
    red[threadIdx.x] = s;
    __syncthreads();
    if (rc == 0)
        out[(g * 8 + ch) * HD + d] = red[d] + red[64 + d] + red[128 + d] + red[192 + d];
}

// ---------------------------------------------------------------------------
// Single-pass fused attention, 3xTF32, (hi,lo)-interleaved K/V SMEM.
// P never touches SMEM: QK^T C-frags are permuted to PV A-frags via quad
// shuffles (owner lane c>>1 -> consumer lane c&3).
// ---------------------------------------------------------------------------
#define AT_S 68
#define SM_F2  (64*AT_S + 64*AT_S)
#define SM_BYTES (SM_F2 * 8)                    // 69632 B

__global__ __launch_bounds__(128, 3) void attn_fused(
    const float* __restrict__ Qp, const float* __restrict__ Kp,
    const float* __restrict__ Vp, const float* __restrict__ KsP,
    float* __restrict__ AO)
{
    extern __shared__ float2 sm2[];
    float2* sK2 = sm2;                    // [64][AT_S]
    float2* sV2 = sK2 + 64 * AT_S;        // [64][AT_S]

    const int tid  = threadIdx.x;
    const int warp = tid >> 5;
    const int lane = tid & 31;
    const int g4   = lane >> 2;
    const int t4   = lane & 3;
    const int qb   = lane & ~3;           // quad base lane

    const int mt  = blockIdx.x;
    const int grp = blockIdx.y;
    const float* Qg = Qp + (size_t)grp * SEQ * HD;
    const float* Kg = Kp + (size_t)grp * SEQ * HD;
    const float* Vg = Vp + (size_t)grp * SEQ * HD;
    float*       Og = AO + (size_t)grp * SEQ * HD;

    const int m0 = mt * 64;
    const int wrow = warp * 16;

    // --- Q fragments (registers) + row means via K column-sums ---
    const int row0 = m0 + wrow + g4;
    const int row1 = row0 + 8;
    uint32_t qah[8][4], qal[8][4];
    float mdot0 = 0.f, mdot1 = 0.f;

    #pragma unroll
    for (int kk = 0; kk < 8; kk++) {
        #pragma unroll
        for (int e = 0; e < 2; e++) {
            const int col = kk * 8 + t4 + e * 4;
            float ks = 0.f;
            #pragma unroll
            for (int c = 0; c < 8; c++)
                ks += KsP[(grp * 8 + c) * HD + col];
            float q0 = Qg[(size_t)row0 * HD + col];
            float q1 = Qg[(size_t)row1 * HD + col];
            mdot0 += q0 * ks;
            mdot1 += q1 * ks;
            float h, l;
            split_tf32(q0 * NORMF, h, l);
            qah[kk][e * 2] = __float_as_uint(h);
            qal[kk][e * 2] = __float_as_uint(l);
            split_tf32(q1 * NORMF, h, l);
            qah[kk][e * 2 + 1] = __float_as_uint(h);
            qal[kk][e * 2 + 1] = __float_as_uint(l);
        }
    }
    #pragma unroll
    for (int o = 1; o <= 2; o <<= 1) {
        mdot0 += __shfl_xor_sync(0xffffffffu, mdot0, o);
        mdot1 += __shfl_xor_sync(0xffffffffu, mdot1, o);
    }
    const float mean0 = mdot0 * (NORMF / (float)SEQ);
    const float mean1 = mdot1 * (NORMF / (float)SEQ);

    // --- streaming loop ---
    float oacc[8][4];
    #pragma unroll
    for (int j = 0; j < 8; j++)
        #pragma unroll
        for (int c = 0; c < 4; c++) oacc[j][c] = 0.f;
    float den0 = 0.f, den1 = 0.f;

    for (int kt = 0; kt < SEQ / 64; kt++) {
        __syncthreads();
        #pragma unroll
        for (int i = 0; i < 8; i++) {
            int j = tid + i * 128;
            int r = j >> 4, c4 = (j & 15) << 2;
            float4 kv = *(const float4*)&Kg[(size_t)(kt * 64 + r) * HD + c4];
            float4 vv = *(const float4*)&Vg[(size_t)(kt * 64 + r) * HD + c4];
            float4 s0, s1;
            split_tf32(kv.x, s0.x, s0.y); split_tf32(kv.y, s0.z, s0.w);
            split_tf32(kv.z, s1.x, s1.y); split_tf32(kv.w, s1.z, s1.w);
            *(float4*)&sK2[r * AT_S + c4]     = s0;
            *(float4*)&sK2[r * AT_S + c4 + 2] = s1;
            split_tf32(vv.x, s0.x, s0.y); split_tf32(vv.y, s0.z, s0.w);
            split_tf32(vv.z, s1.x, s1.y); split_tf32(vv.w, s1.z, s1.w);
            *(float4*)&sV2[r * AT_S + c4]     = s0;
            *(float4*)&sV2[r * AT_S + c4 + 2] = s1;
        }
        __syncthreads();

        // S = Qs @ K^T (3xTF32)
        float sacc[8][4];
        #pragma unroll
        for (int j = 0; j < 8; j++)
            #pragma unroll
            for (int c = 0; c < 4; c++) sacc[j][c] = 0.f;

        #pragma unroll
        for (int kk = 0; kk < 8; kk++) {
            const int k0 = kk * 8;
            #pragma unroll
            for (int j = 0; j < 8; j++) {
                const int brow = j * 8 + g4;
                float2 b0 = sK2[brow * AT_S + k0 + t4];
                float2 b1 = sK2[brow * AT_S + k0 + t4 + 4];
                uint32_t bh[2] = {__float_as_uint(b0.x), __float_as_uint(b1.x)};
                uint32_t bl[2] = {__float_as_uint(b0.y), __float_as_uint(b1.y)};
                mma3(sacc[j], qah[kk], qal[kk], bh, bl);
            }
        }

        // mask + exp in place; accumulate denominators.
        // Layout per j: sacc[j][0]=(row g4, col j*8+2t4), [1]=+1, [2]/[3]= row g4+8.
        #pragma unroll
        for (int j = 0; j < 8; j++) {
            float p0 = (sacc[j][0] > mean0) ? __expf(sacc[j][0]) : 0.f;
            float p1 = (sacc[j][1] > mean0) ? __expf(sacc[j][1]) : 0.f;
            float p2 = (sacc[j][2] > mean1) ? __expf(sacc[j][2]) : 0.f;
            float p3 = (sacc[j][3] > mean1) ? __expf(sacc[j][3]) : 0.f;
            den0 += p0 + p1;
            den1 += p2 + p3;
            sacc[j][0] = p0; sacc[j][1] = p1; sacc[j][2] = p2; sacc[j][3] = p3;
        }

        // O += P @ V: build A-frags by quad shuffle (no SMEM round-trip).
        // Owner of local col c (in block kk): lane qb+(c>>1), reg parity c&1.
        // Consumer t4 needs cols t4 (owner qb+(t4>>1)) and t4+4 (owner +2).
        #pragma unroll
        for (int kk = 0; kk < 8; kk++) {
            const int s1 = qb + (t4 >> 1);
            const int s2 = s1 + 2;
            float v00 = __shfl_sync(0xffffffffu, sacc[kk][0], s1);
            float v01 = __shfl_sync(0xffffffffu, sacc[kk][1], s1);
            float v10 = __shfl_sync(0xffffffffu, sacc[kk][2], s1);
            float v11 = __shfl_sync(0xffffffffu, sacc[kk][3], s1);
            float w00 = __shfl_sync(0xffffffffu, sacc[kk][0], s2);
            float w01 = __shfl_sync(0xffffffffu, sacc[kk][1], s2);
            float w10 = __shfl_sync(0xffffffffu, sacc[kk][2], s2);
            float w11 = __shfl_sync(0xffffffffu, sacc[kk][3], s2);
            const bool odd = (t4 & 1);
            float a0f = odd ? v01 : v00;   // P[g4][t4]
            float a1f = odd ? v11 : v10;   // P[g4+8][t4]
            float a2f = odd ? w01 : w00;   // P[g4][t4+4]
            float a3f = odd ? w11 : w10;   // P[g4+8][t4+4]

            uint32_t ah[4], al[4];
            float h, l;
            split_tf32(a0f, h, l); ah[0] = __float_as_uint(h); al[0] = __float_as_uint(l);
            split_tf32(a1f, h, l); ah[1] = __float_as_uint(h); al[1] = __float_as_uint(l);
            split_tf32(a2f, h, l); ah[2] = __float_as_uint(h); al[2] = __float_as_uint(l);
            split_tf32(a3f, h, l); ah[3] = __float_as_uint(h); al[3] = __float_as_uint(l);

            const int k0 = kk * 8;
            #pragma unroll
            for (int j = 0; j < 8; j++) {
                const int bcol = j * 8 + g4;
                float2 b0 = sV2[(k0 + t4)     * AT_S + bcol];
                float2 b1 = sV2[(k0 + t4 + 4) * AT_S + bcol];
                uint32_t bh[2] = {__float_as_uint(b0.x), __float_as_uint(b1.x)};
                uint32_t bl[2] = {__float_as_uint(b0.y), __float_as_uint(b1.y)};
                mma3(oacc[j], ah, al, bh, bl);
            }
        }
    }

    // reduce denominators, normalize, write out
    #pragma unroll
    for (int o = 1; o <= 2; o <<= 1) {
        den0 += __shfl_xor_sync(0xffffffffu, den0, o);
        den1 += __shfl_xor_sync(0xffffffffu, den1, o);
    }
    const float inv0 = 1.f / den0;
    const float inv1 = 1.f / den1;

    #pragma unroll
    for (int j = 0; j < 8; j++) {
        const int col = j * 8 + 2 * t4;
        *(float2*)&Og[(size_t)row0 * HD + col] =
            make_float2(oacc[j][0] * inv0, oacc[j][1] * inv0);
        *(float2*)&Og[(size_t)row1 * HD + col] =
            make_float2(oacc[j][2] * inv1, oacc[j][3] * inv1);
    }
}

// ---------------------------------------------------------------------------
// Launch
// ---------------------------------------------------------------------------
extern "C" void kernel_launch(void* const* d_in, const int* in_sizes, int n_in,
                              void* d_out, int out_size)
{
    const float* x   = (const float*)d_in[0];
    const float* y   = (const float*)d_in[1];
    const float* q_w = (const float*)d_in[2];
    const float* q_b = (const float*)d_in[3];
    const float* k_w = (const float*)d_in[4];
    const float* k_b = (const float*)d_in[5];
    const float* v_w = (const float*)d_in[6];
    const float* v_b = (const float*)d_in[7];
    const float* o_w = (const float*)d_in[8];
    const float* o_b = (const float*)d_in[9];
    float* out = (float*)d_out;

    float *Qp, *Kp, *Vp, *AO, *KsP;
    cudaGetSymbolAddress((void**)&Qp, g_Qp);
    cudaGetSymbolAddress((void**)&Kp, g_Kp);
    cudaGetSymbolAddress((void**)&Vp, g_Vp);
    cudaGetSymbolAddress((void**)&AO, g_AO);
    cudaGetSymbolAddress((void**)&KsP, g_KsumP);

    static int smem_set = 0;
    if (!smem_set) {
        cudaFuncSetAttribute(attn_fused,
                             cudaFuncAttributeMaxDynamicSharedMemorySize, SM_BYTES);
        cudaFuncSetAttribute(gemm_qkv,
                             cudaFuncAttributeMaxDynamicSharedMemorySize, PJ_SMEM_BYTES);
        cudaFuncSetAttribute(gemm_oproj,
                             cudaFuncAttributeMaxDynamicSharedMemorySize, PJ_SMEM_BYTES);
        smem_set = 1;
    }

    // Fused Q/K/V projections (tensor core, 3xTF32) — one launch, 384 CTAs
    gemm_qkv<<<dim3(4, 32, 3), 256, PJ_SMEM_BYTES>>>(
        x, y, q_w, q_b, k_w, k_b, v_w, v_b, Qp, Kp, Vp);

    // K column-sum partials (for mean thresholds)
    ksum_kernel<<<dim3(NG, 8), 256>>>(Kp, KsP);

    // Fused single-pass attention
    attn_fused<<<dim3(SEQ / 64, NG), 128, SM_BYTES>>>(Qp, Kp, Vp, KsP, AO);

    // Output projection (tensor core, 3xTF32)
    gemm_oproj<<<dim3(4, 32), 256, PJ_SMEM_BYTES>>>(AO, o_w, o_b, out);
}